// round 1
// baseline (speedup 1.0000x reference)
#include <cuda_runtime.h>
#include <cstdint>

// StateDecoder: out[b, r, c] = (x[b, c] >> r) & 1 as float32.
// B = 2048, C = 2048, R = 32. Pure bandwidth problem: 16 MiB in, 512 MiB out.
//
// One thread handles 4 consecutive input words (int4) of one row b.
// For each bit r it stores one float4 into out[b, r, c..c+3].
// Within a warp, threads cover consecutive c-chunks -> every STG.128 group
// forms contiguous 128B sectors (full-line writes, no read-for-ownership).

#define BATCH 2048
#define NUM_CANDIDATES 2048
#define NUM_REPLICAS 32

__global__ __launch_bounds__(256) void state_decoder_kernel(
    const int4* __restrict__ x4,   // [B * C/4]
    float4* __restrict__ out4      // [B * R * C/4]
) {
    constexpr int C4 = NUM_CANDIDATES / 4;  // int4 chunks per row

    const int t = blockIdx.x * blockDim.x + threadIdx.x;   // 0 .. B*C4-1
    const int b = t / C4;
    const int j = t % C4;

    const int4 v = x4[t];
    const unsigned w0 = (unsigned)v.x;
    const unsigned w1 = (unsigned)v.y;
    const unsigned w2 = (unsigned)v.z;
    const unsigned w3 = (unsigned)v.w;

    // Base of out[b, 0, j*4] in float4 units.
    float4* dst = out4 + (size_t)b * (NUM_REPLICAS * C4) + j;

    #pragma unroll
    for (int r = 0; r < NUM_REPLICAS; ++r) {
        // bit -> 0x00000000 or 0x3F800000 (1.0f) without I2F
        unsigned f0 = (0u - ((w0 >> r) & 1u)) & 0x3F800000u;
        unsigned f1 = (0u - ((w1 >> r) & 1u)) & 0x3F800000u;
        unsigned f2 = (0u - ((w2 >> r) & 1u)) & 0x3F800000u;
        unsigned f3 = (0u - ((w3 >> r) & 1u)) & 0x3F800000u;
        float4 f;
        f.x = __uint_as_float(f0);
        f.y = __uint_as_float(f1);
        f.z = __uint_as_float(f2);
        f.w = __uint_as_float(f3);
        dst[(size_t)r * C4] = f;
    }
}

extern "C" void kernel_launch(void* const* d_in, const int* in_sizes, int n_in,
                              void* d_out, int out_size) {
    const int4* x4 = (const int4*)d_in[0];
    float4* out4 = (float4*)d_out;

    constexpr int total_threads = BATCH * (NUM_CANDIDATES / 4);  // 1,048,576
    constexpr int tpb = 256;
    state_decoder_kernel<<<total_threads / tpb, tpb>>>(x4, out4);
}

// round 2
// speedup vs baseline: 1.0259x; 1.0259x over previous
#include <cuda_runtime.h>
#include <cstdint>

// StateDecoder: out[b, r, c] = (x[b, c] >> r) & 1 as float32.
// B = 2048, C = 2048, R = 32. Pure bandwidth: 16 MiB in, 512 MiB out.
//
// One block per batch row b. Each thread owns two int4 chunks of the row,
// at c-offset j and j+1024 (j = tid*4), so every warp-level STG.128 covers a
// fully contiguous 512B span (4 full 128B lines -> no partial-sector writes).
// Stores use __stcs (evict-first streaming) since output is write-once.

#define BATCH 2048
#define NUM_CANDIDATES 2048
#define NUM_REPLICAS 32

__device__ __forceinline__ float4 bits_to_f4(int4 v, int r) {
    // bit -> 0x00000000 or 0x3F800000 (1.0f) without I2F
    unsigned f0 = (0u - (((unsigned)v.x >> r) & 1u)) & 0x3F800000u;
    unsigned f1 = (0u - (((unsigned)v.y >> r) & 1u)) & 0x3F800000u;
    unsigned f2 = (0u - (((unsigned)v.z >> r) & 1u)) & 0x3F800000u;
    unsigned f3 = (0u - (((unsigned)v.w >> r) & 1u)) & 0x3F800000u;
    float4 f;
    f.x = __uint_as_float(f0);
    f.y = __uint_as_float(f1);
    f.z = __uint_as_float(f2);
    f.w = __uint_as_float(f3);
    return f;
}

__global__ __launch_bounds__(256) void state_decoder_kernel(
    const int4* __restrict__ x4,   // [B * C/4]
    float4* __restrict__ out4      // [B * R * C/4]
) {
    constexpr int C4 = NUM_CANDIDATES / 4;   // 512 int4/float4 chunks per row
    constexpr int HALF = C4 / 2;             // 256

    const int b = blockIdx.x;
    const int j = threadIdx.x;               // 0..255 -> chunk j and j+HALF

    const int4 va = x4[(size_t)b * C4 + j];
    const int4 vb = x4[(size_t)b * C4 + j + HALF];

    float4* dst = out4 + (size_t)b * (NUM_REPLICAS * C4) + j;

    #pragma unroll
    for (int r = 0; r < NUM_REPLICAS; ++r) {
        float4 fa = bits_to_f4(va, r);
        float4 fb = bits_to_f4(vb, r);
        __stcs(dst + (size_t)r * C4, fa);
        __stcs(dst + (size_t)r * C4 + HALF, fb);
    }
}

extern "C" void kernel_launch(void* const* d_in, const int* in_sizes, int n_in,
                              void* d_out, int out_size) {
    const int4* x4 = (const int4*)d_in[0];
    float4* out4 = (float4*)d_out;

    state_decoder_kernel<<<BATCH, 256>>>(x4, out4);
}